// round 16
// baseline (speedup 1.0000x reference)
#include <cuda_runtime.h>
#include <cuda_fp16.h>
#include <cstdint>
#include <cstddef>

// ---------------------------------------------------------------------------
// SamplingBottleneckModule on GB300 — fp16 HMMA GEMM (BK=64, 8 warps, 2-stage),
// fp16 logits intermediate, coalesced epilogue with store-early ordering
// (minimizes live registers: no spills, higher occupancy).
// ---------------------------------------------------------------------------

#define ROWS_TOTAL 32768
#define NCLS 512
#define KDIM 512
#define NFUSED 1024
#define KSEQ 8.0f

__device__ __align__(256) __half2 g_logits[(size_t)ROWS_TOTAL * 512];  // 64 MiB
__device__ __align__(256) __half2 g_ahi[(size_t)ROWS_TOTAL * 256];     // 32 MiB
__device__ __align__(256) __half2 g_bhi[(size_t)NFUSED * 256];         // 1 MiB

// ---------------------------------------------------------------------------
__device__ __forceinline__ uint32_t smem_u32(const void* p) {
    uint32_t a;
    asm("{ .reg .u64 t; cvta.to.shared.u64 t, %1; cvt.u32.u64 %0, t; }"
        : "=r"(a) : "l"(p));
    return a;
}
__device__ __forceinline__ void cp16(uint32_t dst, const void* src) {
    asm volatile("cp.async.cg.shared.global [%0], [%1], 16;"
                 :: "r"(dst), "l"(src) : "memory");
}
__device__ __forceinline__ void ldsm4(uint32_t* r, uint32_t addr) {
    asm volatile("ldmatrix.sync.aligned.m8n8.x4.shared.b16 {%0,%1,%2,%3}, [%4];"
                 : "=r"(r[0]), "=r"(r[1]), "=r"(r[2]), "=r"(r[3]) : "r"(addr));
}
__device__ __forceinline__ void mma_f16(float* c, const uint32_t* a,
                                        const uint32_t* b) {
    asm volatile(
        "mma.sync.aligned.m16n8k16.row.col.f32.f16.f16.f32 "
        "{%0,%1,%2,%3},{%4,%5,%6,%7},{%8,%9},{%0,%1,%2,%3};"
        : "+f"(c[0]), "+f"(c[1]), "+f"(c[2]), "+f"(c[3])
        : "r"(a[0]), "r"(a[1]), "r"(a[2]), "r"(a[3]), "r"(b[0]), "r"(b[1]));
}

// ---------------------------------------------------------------------------
// Convert kernel: 16 floats per thread (4x float4 -> 2x uint4 of half2).
// ---------------------------------------------------------------------------
__global__ __launch_bounds__(256)
void convert_kernel(const float* __restrict__ X,
                    const float* __restrict__ WB,
                    const float* __restrict__ WV)
{
    const size_t t = (size_t)blockIdx.x * 256 + threadIdx.x;
    const float* src;
    __half2* dst;
    if (t < 1048576) {                       // x chunks
        src = X + t * 16;
        dst = g_ahi + t * 8;
    } else {                                 // w chunks
        const size_t u = t - 1048576;        // 0..32767
        const int n = (int)(u >> 5);         // fused row 0..1023
        const int off = (int)(u & 31) * 16;  // float offset in row
        src = ((n < NCLS) ? (WB + (size_t)n * KDIM)
                          : (WV + (size_t)(n - NCLS) * KDIM)) + off;
        dst = g_bhi + (size_t)n * 256 + off / 2;
    }

    __half2 h[8];
#pragma unroll
    for (int q = 0; q < 4; q++) {
        float4 v = reinterpret_cast<const float4*>(src)[q];
        h[2 * q].x     = __float2half(v.x);
        h[2 * q].y     = __float2half(v.y);
        h[2 * q + 1].x = __float2half(v.z);
        h[2 * q + 1].y = __float2half(v.w);
    }
    uint4* d4 = reinterpret_cast<uint4*>(dst);
    d4[0] = *reinterpret_cast<uint4*>(&h[0]);
    d4[1] = *reinterpret_cast<uint4*>(&h[4]);
}

// ---------------------------------------------------------------------------
// HMMA GEMM: 128x128 CTA tile, BK=64, 2-stage cp.async, 256 threads.
// ---------------------------------------------------------------------------
#define BK 64
#define NIT (KDIM / BK)            // 8
#define RB 144
#define MATB (128 * RB)            // 18432
#define STAGEB (2 * MATB)          // 36864
#define SMEM_GEMM (2 * STAGEB)     // 73728

__device__ __forceinline__ void load_stage(uint32_t sb, int s, int it,
                                           int m0, int n0, int tid)
{
    const int k0 = it * BK;
    const char* ah = (const char*)g_ahi;
    const char* bh = (const char*)g_bhi;
    const uint32_t stb = sb + s * STAGEB;

#pragma unroll
    for (int i = 0; i < 8; i++) {
        const int t = tid + i * 256;          // 0..2047
        const int mat = t >> 10;              // 0 or 1
        const int idx = t & 1023;
        const int row = idx >> 3;
        const int seg = idx & 7;
        const char* base = mat ? bh : ah;
        const size_t grow = (size_t)((mat ? n0 : m0) + row);
        const char* src = base + (grow * KDIM + k0) * 2 + seg * 16;
        const uint32_t dst = stb + mat * MATB + row * RB + seg * 16;
        cp16(dst, src);
    }
    asm volatile("cp.async.commit_group;" ::: "memory");
}

__global__ __launch_bounds__(256, 2)
void gemm_hmma_kernel()
{
    extern __shared__ char smem[];
    const uint32_t sb = smem_u32(smem);
    const int tid = threadIdx.x;
    const int lane = tid & 31;
    const int wid = tid >> 5;
    const int m0 = blockIdx.y * 128;
    const int n0 = blockIdx.x * 128;
    const int wm = (wid >> 2) * 64;     // warp m offset
    const int wn = (wid & 3) * 32;      // warp n offset

    const uint32_t aoff = (uint32_t)((wm + (lane & 15)) * RB + ((lane >> 4) << 4));
    const uint32_t boff = (uint32_t)((wn + (lane & 7) + ((lane >> 4) << 3)) * RB
                                     + (((lane >> 3) & 1) << 4));

    float acc[4][4][4];
#pragma unroll
    for (int i = 0; i < 4; i++)
#pragma unroll
        for (int j = 0; j < 4; j++)
#pragma unroll
            for (int r = 0; r < 4; r++) acc[i][j][r] = 0.0f;

    load_stage(sb, 0, 0, m0, n0, tid);
    load_stage(sb, 1, 1, m0, n0, tid);

#pragma unroll 1
    for (int it = 0; it < NIT; it++) {
        const int s = it & 1;
        asm volatile("cp.async.wait_group 1;" ::: "memory");
        __syncthreads();

        const uint32_t Ah = sb + s * STAGEB + aoff;
        const uint32_t Bh = sb + s * STAGEB + MATB + boff;

#pragma unroll
        for (int kk = 0; kk < 4; kk++) {
            const uint32_t kb = kk << 5;        // 0,32,64,96
            uint32_t a[4][4], b[4][2];

#pragma unroll
            for (int i = 0; i < 4; i++) ldsm4(a[i], Ah + i * (16 * RB) + kb);
#pragma unroll
            for (int jj = 0; jj < 2; jj++) {
                uint32_t r[4];
                ldsm4(r, Bh + jj * (16 * RB) + kb);
                b[2 * jj][0] = r[0]; b[2 * jj][1] = r[1];
                b[2 * jj + 1][0] = r[2]; b[2 * jj + 1][1] = r[3];
            }
#pragma unroll
            for (int i = 0; i < 4; i++)
#pragma unroll
                for (int j = 0; j < 4; j++) mma_f16(acc[i][j], a[i], b[j]);
        }

        __syncthreads();
        if (it + 2 < NIT) {
            load_stage(sb, s, it + 2, m0, n0, tid);
        } else {
            asm volatile("cp.async.commit_group;" ::: "memory");  // keep count
        }
    }

    // Write accumulators to fp16 logits.
    const int rbase = m0 + wm + (lane >> 2);
    const int cbase = wn + 2 * (lane & 3) + n0;   // even
#pragma unroll
    for (int i = 0; i < 4; i++) {
#pragma unroll
        for (int j = 0; j < 4; j++) {
            const int r = rbase + i * 16;
            const int c = cbase + j * 8;
            g_logits[(size_t)r * 512 + (c >> 1)] =
                __floats2half2_rn(acc[i][j][0], acc[i][j][1]);
            g_logits[(size_t)(r + 8) * 512 + (c >> 1)] =
                __floats2half2_rn(acc[i][j][2], acc[i][j][3]);
        }
    }
}

// ---------------------------------------------------------------------------
// Per-row epilogue: one warp/row; lane owns 4 groups of 4 contiguous classes
// (class = 4*(q*32+lane)+e): all loads/stores fully coalesced.
// Store-early ordering keeps peak live registers ~40 floats (no spills):
//   softmax1 -> p;  softmax2 -> store values (frees v);  y = log(1-p);
//   cumsum(p) -> store (frees p);  Newton(y) -> alpha;  marginals -> store.
// No max-subtraction (logits bounded).
// ---------------------------------------------------------------------------
__global__ __launch_bounds__(256)
void epilogue_kernel(float* __restrict__ out)
{
    const int warp = threadIdx.x >> 5;
    const int lane = threadIdx.x & 31;
    const int row = blockIdx.x * 8 + warp;

    const __half2* lrow = g_logits + (size_t)row * 512;
    const uint2* L1 = reinterpret_cast<const uint2*>(lrow);        // 128 uint2
    const uint2* L2 = reinterpret_cast<const uint2*>(lrow + 256);

    const size_t BTN = (size_t)ROWS_TOTAL * NCLS;
    float4* OM = reinterpret_cast<float4*>(out + (size_t)row * NCLS);
    float4* OV = reinterpret_cast<float4*>(out + BTN + (size_t)row * NCLS);
    float4* OC = reinterpret_cast<float4*>(out + 2 * BTN + (size_t)row * NCLS);

    // ---- softmax1 -> p (no max shift) ----
    float p[16];
    float s = 0.0f;
#pragma unroll
    for (int q = 0; q < 4; q++) {
        uint2 u = L1[q * 32 + lane];
        float2 a0 = __half22float2(*reinterpret_cast<const __half2*>(&u.x));
        float2 a1 = __half22float2(*reinterpret_cast<const __half2*>(&u.y));
        p[4 * q + 0] = __expf(a0.x);
        p[4 * q + 1] = __expf(a0.y);
        p[4 * q + 2] = __expf(a1.x);
        p[4 * q + 3] = __expf(a1.y);
        s += p[4 * q] + p[4 * q + 1] + p[4 * q + 2] + p[4 * q + 3];
    }
#pragma unroll
    for (int o = 16; o > 0; o >>= 1)
        s += __shfl_xor_sync(0xFFFFFFFFu, s, o);
    const float inv = 1.0f / s;
#pragma unroll
    for (int i = 0; i < 16; i++) p[i] *= inv;

    // ---- softmax2 -> values; store immediately (short live range) ----
    {
        float v[16];
        float s2 = 0.0f;
#pragma unroll
        for (int q = 0; q < 4; q++) {
            uint2 u = L2[q * 32 + lane];
            float2 b0 = __half22float2(*reinterpret_cast<const __half2*>(&u.x));
            float2 b1 = __half22float2(*reinterpret_cast<const __half2*>(&u.y));
            v[4 * q + 0] = __expf(p[4 * q + 0] + b0.x);
            v[4 * q + 1] = __expf(p[4 * q + 1] + b0.y);
            v[4 * q + 2] = __expf(p[4 * q + 2] + b1.x);
            v[4 * q + 3] = __expf(p[4 * q + 3] + b1.y);
            s2 += v[4 * q] + v[4 * q + 1] + v[4 * q + 2] + v[4 * q + 3];
        }
#pragma unroll
        for (int o = 16; o > 0; o >>= 1)
            s2 += __shfl_xor_sync(0xFFFFFFFFu, s2, o);
        const float inv2 = 1.0f / s2;
#pragma unroll
        for (int q = 0; q < 4; q++)
            OV[q * 32 + lane] = make_float4(v[4 * q] * inv2, v[4 * q + 1] * inv2,
                                            v[4 * q + 2] * inv2, v[4 * q + 3] * inv2);
    }

    // ---- y = log(1 - p) (needed by Newton; p still live for cumsum) ----
    float y[16];
#pragma unroll
    for (int i = 0; i < 16; i++) y[i] = __logf(1.0f - p[i]);

    // ---- exclusive cumsum of p; store (frees p) ----
    {
        float running = 0.0f;
#pragma unroll
        for (int q = 0; q < 4; q++) {
            const float t = p[4 * q] + p[4 * q + 1] + p[4 * q + 2] + p[4 * q + 3];
            float incl = t;
#pragma unroll
            for (int o = 1; o < 32; o <<= 1) {
                const float nv = __shfl_up_sync(0xFFFFFFFFu, incl, o);
                if (lane >= o) incl += nv;
            }
            float c = running + incl - t;
            float4 oc;
            oc.x = c;               c += p[4 * q];
            oc.y = c;               c += p[4 * q + 1];
            oc.z = c;               c += p[4 * q + 2];
            oc.w = c;
            OC[q * 32 + lane] = oc;
            running += __shfl_sync(0xFFFFFFFFu, incl, 31);
        }
    }

    // ---- Newton for alpha (only y live) ----
    float alpha = KSEQ;
#pragma unroll
    for (int it = 0; it < 3; it++) {
        float se = 0.0f, sd = 0.0f;
#pragma unroll
        for (int i = 0; i < 16; i++) {
            const float e = __expf(alpha * y[i]);
            se += e;
            sd += e * y[i];
        }
#pragma unroll
        for (int o = 16; o > 0; o >>= 1) {
            se += __shfl_xor_sync(0xFFFFFFFFu, se, o);
            sd += __shfl_xor_sync(0xFFFFFFFFu, sd, o);
        }
        alpha -= (se + (KSEQ - (float)NCLS)) / sd;
    }

    // ---- marginals = 1 - exp(alpha*y); store ----
#pragma unroll
    for (int q = 0; q < 4; q++) {
        OM[q * 32 + lane] = make_float4(
            1.0f - __expf(alpha * y[4 * q + 0]),
            1.0f - __expf(alpha * y[4 * q + 1]),
            1.0f - __expf(alpha * y[4 * q + 2]),
            1.0f - __expf(alpha * y[4 * q + 3]));
    }
}

// ---------------------------------------------------------------------------
extern "C" void kernel_launch(void* const* d_in, const int* in_sizes, int n_in,
                              void* d_out, int out_size)
{
    const float* x  = (const float*)d_in[0];
    const float* wb = (const float*)d_in[1];
    const float* wv = (const float*)d_in[2];
    float* out = (float*)d_out;
    (void)n_in; (void)out_size; (void)in_sizes;

    static bool configured = false;
    if (!configured) {
        cudaFuncSetAttribute(gemm_hmma_kernel,
                             cudaFuncAttributeMaxDynamicSharedMemorySize,
                             SMEM_GEMM);
        configured = true;
    }

    convert_kernel<<<(1048576 + 32768) / 256, 256>>>(x, wb, wv);

    dim3 grid(NFUSED / 128, ROWS_TOTAL / 128);   // (8, 256)
    gemm_hmma_kernel<<<grid, 256, SMEM_GEMM>>>();

    epilogue_kernel<<<ROWS_TOTAL / 8, 256>>>(out);
}

// round 17
// speedup vs baseline: 1.0421x; 1.0421x over previous
#include <cuda_runtime.h>
#include <cuda_fp16.h>
#include <cstdint>
#include <cstddef>

// ---------------------------------------------------------------------------
// SamplingBottleneckModule on GB300 — fp16 HMMA GEMM (BK=64, 8 warps,
// 3-buffer ring / prefetch-2 / SINGLE __syncthreads per iteration),
// fp16 logits intermediate, coalesced store-early epilogue.
// ---------------------------------------------------------------------------

#define ROWS_TOTAL 32768
#define NCLS 512
#define KDIM 512
#define NFUSED 1024
#define KSEQ 8.0f

__device__ __align__(256) __half2 g_logits[(size_t)ROWS_TOTAL * 512];  // 64 MiB
__device__ __align__(256) __half2 g_ahi[(size_t)ROWS_TOTAL * 256];     // 32 MiB
__device__ __align__(256) __half2 g_bhi[(size_t)NFUSED * 256];         // 1 MiB

// ---------------------------------------------------------------------------
__device__ __forceinline__ uint32_t smem_u32(const void* p) {
    uint32_t a;
    asm("{ .reg .u64 t; cvta.to.shared.u64 t, %1; cvt.u32.u64 %0, t; }"
        : "=r"(a) : "l"(p));
    return a;
}
__device__ __forceinline__ void cp16(uint32_t dst, const void* src) {
    asm volatile("cp.async.cg.shared.global [%0], [%1], 16;"
                 :: "r"(dst), "l"(src) : "memory");
}
__device__ __forceinline__ void ldsm4(uint32_t* r, uint32_t addr) {
    asm volatile("ldmatrix.sync.aligned.m8n8.x4.shared.b16 {%0,%1,%2,%3}, [%4];"
                 : "=r"(r[0]), "=r"(r[1]), "=r"(r[2]), "=r"(r[3]) : "r"(addr));
}
__device__ __forceinline__ void mma_f16(float* c, const uint32_t* a,
                                        const uint32_t* b) {
    asm volatile(
        "mma.sync.aligned.m16n8k16.row.col.f32.f16.f16.f32 "
        "{%0,%1,%2,%3},{%4,%5,%6,%7},{%8,%9},{%0,%1,%2,%3};"
        : "+f"(c[0]), "+f"(c[1]), "+f"(c[2]), "+f"(c[3])
        : "r"(a[0]), "r"(a[1]), "r"(a[2]), "r"(a[3]), "r"(b[0]), "r"(b[1]));
}

// ---------------------------------------------------------------------------
// Convert kernel: 16 floats per thread (4x float4 -> 2x uint4 of half2).
// ---------------------------------------------------------------------------
__global__ __launch_bounds__(256)
void convert_kernel(const float* __restrict__ X,
                    const float* __restrict__ WB,
                    const float* __restrict__ WV)
{
    const size_t t = (size_t)blockIdx.x * 256 + threadIdx.x;
    const float* src;
    __half2* dst;
    if (t < 1048576) {                       // x chunks
        src = X + t * 16;
        dst = g_ahi + t * 8;
    } else {                                 // w chunks
        const size_t u = t - 1048576;        // 0..32767
        const int n = (int)(u >> 5);         // fused row 0..1023
        const int off = (int)(u & 31) * 16;  // float offset in row
        src = ((n < NCLS) ? (WB + (size_t)n * KDIM)
                          : (WV + (size_t)(n - NCLS) * KDIM)) + off;
        dst = g_bhi + (size_t)n * 256 + off / 2;
    }

    __half2 h[8];
#pragma unroll
    for (int q = 0; q < 4; q++) {
        float4 v = reinterpret_cast<const float4*>(src)[q];
        h[2 * q].x     = __float2half(v.x);
        h[2 * q].y     = __float2half(v.y);
        h[2 * q + 1].x = __float2half(v.z);
        h[2 * q + 1].y = __float2half(v.w);
    }
    uint4* d4 = reinterpret_cast<uint4*>(dst);
    d4[0] = *reinterpret_cast<uint4*>(&h[0]);
    d4[1] = *reinterpret_cast<uint4*>(&h[4]);
}

// ---------------------------------------------------------------------------
// HMMA GEMM: 128x128 CTA tile, BK=64, 3-buffer ring (prefetch depth 2),
// ONE __syncthreads per iteration. 256 threads, 8 warps (2m x 4n).
// ---------------------------------------------------------------------------
#define BK 64
#define NIT (KDIM / BK)            // 8
#define RB 144
#define MATB (128 * RB)            // 18432
#define STAGEB (2 * MATB)          // 36864
#define NSTAGE 3
#define SMEM_GEMM (NSTAGE * STAGEB) // 110592

__device__ __forceinline__ void load_stage(uint32_t sb, int s, int it,
                                           int m0, int n0, int tid)
{
    const int k0 = it * BK;
    const char* ah = (const char*)g_ahi;
    const char* bh = (const char*)g_bhi;
    const uint32_t stb = sb + s * STAGEB;

#pragma unroll
    for (int i = 0; i < 8; i++) {
        const int t = tid + i * 256;          // 0..2047
        const int mat = t >> 10;              // 0 or 1
        const int idx = t & 1023;
        const int row = idx >> 3;
        const int seg = idx & 7;
        const char* base = mat ? bh : ah;
        const size_t grow = (size_t)((mat ? n0 : m0) + row);
        const char* src = base + (grow * KDIM + k0) * 2 + seg * 16;
        const uint32_t dst = stb + mat * MATB + row * RB + seg * 16;
        cp16(dst, src);
    }
    asm volatile("cp.async.commit_group;" ::: "memory");
}

__global__ __launch_bounds__(256, 2)
void gemm_hmma_kernel()
{
    extern __shared__ char smem[];
    const uint32_t sb = smem_u32(smem);
    const int tid = threadIdx.x;
    const int lane = tid & 31;
    const int wid = tid >> 5;
    const int m0 = blockIdx.y * 128;
    const int n0 = blockIdx.x * 128;
    const int wm = (wid >> 2) * 64;     // warp m offset
    const int wn = (wid & 3) * 32;      // warp n offset

    const uint32_t aoff = (uint32_t)((wm + (lane & 15)) * RB + ((lane >> 4) << 4));
    const uint32_t boff = (uint32_t)((wn + (lane & 7) + ((lane >> 4) << 3)) * RB
                                     + (((lane >> 3) & 1) << 4));

    float acc[4][4][4];
#pragma unroll
    for (int i = 0; i < 4; i++)
#pragma unroll
        for (int j = 0; j < 4; j++)
#pragma unroll
            for (int r = 0; r < 4; r++) acc[i][j][r] = 0.0f;

    // 3-buffer ring, prefetch depth 2: buffers it%3.
    load_stage(sb, 0, 0, m0, n0, tid);
    load_stage(sb, 1, 1, m0, n0, tid);

    int s = 0;
#pragma unroll 1
    for (int it = 0; it < NIT; it++) {
        asm volatile("cp.async.wait_group 1;" ::: "memory");
        __syncthreads();   // stage 'it' visible; everyone past MMA(it-1)

        const uint32_t Ah = sb + s * STAGEB + aoff;
        const uint32_t Bh = sb + s * STAGEB + MATB + boff;

#pragma unroll
        for (int kk = 0; kk < 4; kk++) {
            const uint32_t kb = kk << 5;        // 0,32,64,96
            uint32_t a[4][4], b[4][2];

#pragma unroll
            for (int i = 0; i < 4; i++) ldsm4(a[i], Ah + i * (16 * RB) + kb);
#pragma unroll
            for (int jj = 0; jj < 2; jj++) {
                uint32_t r[4];
                ldsm4(r, Bh + jj * (16 * RB) + kb);
                b[2 * jj][0] = r[0]; b[2 * jj][1] = r[1];
                b[2 * jj + 1][0] = r[2]; b[2 * jj + 1][1] = r[3];
            }
#pragma unroll
            for (int i = 0; i < 4; i++)
#pragma unroll
                for (int j = 0; j < 4; j++) mma_f16(acc[i][j], a[i], b[j]);
        }

        // No bottom barrier: prefetch (it+2) writes buffer (it+2)%3, which
        // differs from the read buffer it%3 and (it+1)%3, and was last read
        // in MMA(it-1) — everyone passed that at this iteration's top sync.
        if (it + 2 < NIT) {
            const int wbuf = (it + 2) % 3;
            load_stage(sb, wbuf, it + 2, m0, n0, tid);
        } else {
            asm volatile("cp.async.commit_group;" ::: "memory");  // keep count
        }
        s = (s == 2) ? 0 : s + 1;
    }

    // Write accumulators to fp16 logits.
    const int rbase = m0 + wm + (lane >> 2);
    const int cbase = wn + 2 * (lane & 3) + n0;   // even
#pragma unroll
    for (int i = 0; i < 4; i++) {
#pragma unroll
        for (int j = 0; j < 4; j++) {
            const int r = rbase + i * 16;
            const int c = cbase + j * 8;
            g_logits[(size_t)r * 512 + (c >> 1)] =
                __floats2half2_rn(acc[i][j][0], acc[i][j][1]);
            g_logits[(size_t)(r + 8) * 512 + (c >> 1)] =
                __floats2half2_rn(acc[i][j][2], acc[i][j][3]);
        }
    }
}

// ---------------------------------------------------------------------------
// Per-row epilogue: one warp/row; lane owns 4 groups of 4 contiguous classes
// (class = 4*(q*32+lane)+e): fully coalesced loads/stores, store-early
// ordering, no max-subtraction (logits bounded).
// ---------------------------------------------------------------------------
__global__ __launch_bounds__(256)
void epilogue_kernel(float* __restrict__ out)
{
    const int warp = threadIdx.x >> 5;
    const int lane = threadIdx.x & 31;
    const int row = blockIdx.x * 8 + warp;

    const __half2* lrow = g_logits + (size_t)row * 512;
    const uint2* L1 = reinterpret_cast<const uint2*>(lrow);        // 128 uint2
    const uint2* L2 = reinterpret_cast<const uint2*>(lrow + 256);

    const size_t BTN = (size_t)ROWS_TOTAL * NCLS;
    float4* OM = reinterpret_cast<float4*>(out + (size_t)row * NCLS);
    float4* OV = reinterpret_cast<float4*>(out + BTN + (size_t)row * NCLS);
    float4* OC = reinterpret_cast<float4*>(out + 2 * BTN + (size_t)row * NCLS);

    // ---- softmax1 -> p (no max shift) ----
    float p[16];
    float s = 0.0f;
#pragma unroll
    for (int q = 0; q < 4; q++) {
        uint2 u = L1[q * 32 + lane];
        float2 a0 = __half22float2(*reinterpret_cast<const __half2*>(&u.x));
        float2 a1 = __half22float2(*reinterpret_cast<const __half2*>(&u.y));
        p[4 * q + 0] = __expf(a0.x);
        p[4 * q + 1] = __expf(a0.y);
        p[4 * q + 2] = __expf(a1.x);
        p[4 * q + 3] = __expf(a1.y);
        s += p[4 * q] + p[4 * q + 1] + p[4 * q + 2] + p[4 * q + 3];
    }
#pragma unroll
    for (int o = 16; o > 0; o >>= 1)
        s += __shfl_xor_sync(0xFFFFFFFFu, s, o);
    const float inv = 1.0f / s;
#pragma unroll
    for (int i = 0; i < 16; i++) p[i] *= inv;

    // ---- softmax2 -> values; store immediately ----
    {
        float v[16];
        float s2 = 0.0f;
#pragma unroll
        for (int q = 0; q < 4; q++) {
            uint2 u = L2[q * 32 + lane];
            float2 b0 = __half22float2(*reinterpret_cast<const __half2*>(&u.x));
            float2 b1 = __half22float2(*reinterpret_cast<const __half2*>(&u.y));
            v[4 * q + 0] = __expf(p[4 * q + 0] + b0.x);
            v[4 * q + 1] = __expf(p[4 * q + 1] + b0.y);
            v[4 * q + 2] = __expf(p[4 * q + 2] + b1.x);
            v[4 * q + 3] = __expf(p[4 * q + 3] + b1.y);
            s2 += v[4 * q] + v[4 * q + 1] + v[4 * q + 2] + v[4 * q + 3];
        }
#pragma unroll
        for (int o = 16; o > 0; o >>= 1)
            s2 += __shfl_xor_sync(0xFFFFFFFFu, s2, o);
        const float inv2 = 1.0f / s2;
#pragma unroll
        for (int q = 0; q < 4; q++)
            OV[q * 32 + lane] = make_float4(v[4 * q] * inv2, v[4 * q + 1] * inv2,
                                            v[4 * q + 2] * inv2, v[4 * q + 3] * inv2);
    }

    // ---- y = log(1 - p) ----
    float y[16];
#pragma unroll
    for (int i = 0; i < 16; i++) y[i] = __logf(1.0f - p[i]);

    // ---- exclusive cumsum of p; store (frees p) ----
    {
        float running = 0.0f;
#pragma unroll
        for (int q = 0; q < 4; q++) {
            const float t = p[4 * q] + p[4 * q + 1] + p[4 * q + 2] + p[4 * q + 3];
            float incl = t;
#pragma unroll
            for (int o = 1; o < 32; o <<= 1) {
                const float nv = __shfl_up_sync(0xFFFFFFFFu, incl, o);
                if (lane >= o) incl += nv;
            }
            float c = running + incl - t;
            float4 oc;
            oc.x = c;               c += p[4 * q];
            oc.y = c;               c += p[4 * q + 1];
            oc.z = c;               c += p[4 * q + 2];
            oc.w = c;
            OC[q * 32 + lane] = oc;
            running += __shfl_sync(0xFFFFFFFFu, incl, 31);
        }
    }

    // ---- Newton for alpha (only y live) ----
    float alpha = KSEQ;
#pragma unroll
    for (int it = 0; it < 3; it++) {
        float se = 0.0f, sd = 0.0f;
#pragma unroll
        for (int i = 0; i < 16; i++) {
            const float e = __expf(alpha * y[i]);
            se += e;
            sd += e * y[i];
        }
#pragma unroll
        for (int o = 16; o > 0; o >>= 1) {
            se += __shfl_xor_sync(0xFFFFFFFFu, se, o);
            sd += __shfl_xor_sync(0xFFFFFFFFu, sd, o);
        }
        alpha -= (se + (KSEQ - (float)NCLS)) / sd;
    }

    // ---- marginals = 1 - exp(alpha*y); store ----
#pragma unroll
    for (int q = 0; q < 4; q++) {
        OM[q * 32 + lane] = make_float4(
            1.0f - __expf(alpha * y[4 * q + 0]),
            1.0f - __expf(alpha * y[4 * q + 1]),
            1.0f - __expf(alpha * y[4 * q + 2]),
            1.0f - __expf(alpha * y[4 * q + 3]));
    }
}

// ---------------------------------------------------------------------------
extern "C" void kernel_launch(void* const* d_in, const int* in_sizes, int n_in,
                              void* d_out, int out_size)
{
    const float* x  = (const float*)d_in[0];
    const float* wb = (const float*)d_in[1];
    const float* wv = (const float*)d_in[2];
    float* out = (float*)d_out;
    (void)n_in; (void)out_size; (void)in_sizes;

    static bool configured = false;
    if (!configured) {
        cudaFuncSetAttribute(gemm_hmma_kernel,
                             cudaFuncAttributeMaxDynamicSharedMemorySize,
                             SMEM_GEMM);
        configured = true;
    }

    convert_kernel<<<(1048576 + 32768) / 256, 256>>>(x, wb, wv);

    dim3 grid(NFUSED / 128, ROWS_TOTAL / 128);   // (8, 256)
    gemm_hmma_kernel<<<grid, 256, SMEM_GEMM>>>();

    epilogue_kernel<<<ROWS_TOTAL / 8, 256>>>(out);
}